// round 6
// baseline (speedup 1.0000x reference)
#include <cuda_runtime.h>
#include <cstdint>

// ---------------------------------------------------------------------------
// KAN 2-layer fused, round 6: g-major K layout -> constant-stride producers.
//   D[o,b] = sum_{i,g} W[o,i,g] * f_g(x[b,i])
//   f = {basis_0..7(x), silu(x)},  W = {ssp*coef_0..7, sb}
//   Chunk of 8 inputs: kk = g*8 + ii  (ks = g in 0..8, kc = ii in 0..7)
//   K2: per CTA M=128 (o), N=128 (b), K=432;  grid (2 o-tiles, 64 k-splits)
// ---------------------------------------------------------------------------

#define B_     128
#define IN_    3072
#define H_     256
#define OUT_   10
#define KSPLIT 64
#define IPC    48          // inputs per CTA
#define NCH    6           // chunks of 8 inputs
#define NKS    9           // k-steps of 8 per chunk (9 feature planes)

__device__ float g_Y1p[KSPLIT * B_ * H_];    // layer-1 partials [split][b][o]
__device__ float g_Y1[B_ * H_];              // reduced layer-1 pre-activation

// ---- dynamic smem layout ---------------------------------------------------
#define XS_PITCH 49
#define SM_XS    0
#define SM_A0    25088
#define SM_B0    (SM_A0 + 36864)
#define SM_A1    (SM_B0 + 36864)
#define SM_B1    (SM_A1 + 36864)
#define SMEM_TOTAL (SM_B1 + 36864)
#define SP       132

// ---- helpers ---------------------------------------------------------------
__device__ __forceinline__ uint32_t tf32r(float x) {
    uint32_t r;
    asm("cvt.rna.tf32.f32 %0, %1;" : "=r"(r) : "f"(x));
    return r;
}
__device__ __forceinline__ void mma8(float d[4], const uint32_t a[4], const uint32_t b[2]) {
    asm volatile("mma.sync.aligned.m16n8k8.row.col.f32.tf32.tf32.f32 "
        "{%0,%1,%2,%3}, {%4,%5,%6,%7}, {%8,%9}, {%0,%1,%2,%3};"
        : "+f"(d[0]), "+f"(d[1]), "+f"(d[2]), "+f"(d[3])
        : "r"(a[0]), "r"(a[1]), "r"(a[2]), "r"(a[3]), "r"(b[0]), "r"(b[1]));
}
__device__ __forceinline__ float silu_f(float x) { return x / (1.0f + __expf(-x)); }
__device__ __forceinline__ float selu_f(float x) {
    const float scale = 1.0507009873554805f;
    const float alpha = 1.6732632423543772f;
    return x > 0.0f ? scale * x : scale * alpha * expm1f(x);
}

// Closed-form cubic B-spline on uniform extended grid t_j = -2.2 + 0.4 j.
// For x in [t_m, t_m+1): nonzero cubics are indices m-3..m with cardinal
// weights w0..w3 (validated rounds 4-5 against Cox-de-Boor).
struct Bsp { float w0, w1, w2, w3; int m; };
__device__ __forceinline__ Bsp bspline4(float x) {
    Bsp r;
    float tpos = (x + 2.2f) * 2.5f;
    float mf = floorf(tpos);
    r.m = (int)mf;
    float u = tpos - mf;
    float u2 = u * u, u3 = u2 * u, om = 1.0f - u;
    bool valid = (x >= -2.2f) && (r.m <= 10);
    float s = valid ? (1.0f / 6.0f) : 0.0f;
    r.w0 = om * om * om * s;
    r.w1 = (3.0f * u3 - 6.0f * u2 + 4.0f) * s;
    r.w2 = (-3.0f * u3 + 3.0f * u2 + 3.0f * u + 1.0f) * s;
    r.w3 = u3 * s;
    return r;
}
__device__ __forceinline__ float bsp_at(const Bsp& r, int g) {
    int d = r.m - g;
    float v = 0.0f;
    v = (d == 3) ? r.w0 : v;
    v = (d == 2) ? r.w1 : v;
    v = (d == 1) ? r.w2 : v;
    v = (d == 0) ? r.w3 : v;
    return v;
}

// ---------------------------------------------------------------------------
// K2: layer-1 GEMM on mma.sync. g-major K: plane stride = 1024 u32 (4KB)
// for both A ([ks][mt8][lane][word4]) and B ([ks][nt16][lane][word2]).
// ---------------------------------------------------------------------------
__global__ void __launch_bounds__(256, 1) k2_mma(const float* __restrict__ x,
                                                const float* __restrict__ coef1,
                                                const float* __restrict__ sb1,
                                                const float* __restrict__ ssp1) {
    extern __shared__ __align__(16) char smem[];
    float* xs = (float*)(smem + SM_XS);

    const int tid  = threadIdx.x;
    const int lane = tid & 31;
    const int wid  = tid >> 5;
    const int wm   = wid >> 2;
    const int wn   = wid & 3;
    const int o0   = blockIdx.x * 128;
    const int split = blockIdx.y;
    const int i0   = split * IPC;

    for (int idx = tid; idx < B_ * IPC; idx += 256) {
        int b = idx / IPC, c = idx % IPC;
        xs[b * XS_PITCH + c] = x[b * IN_ + i0 + c];
    }

    float acc[4][4][4];
#pragma unroll
    for (int mi = 0; mi < 4; mi++)
#pragma unroll
        for (int ni = 0; ni < 4; ni++)
#pragma unroll
            for (int w = 0; w < 4; w++) acc[mi][ni][w] = 0.0f;

    float4 pc0[4], pc1[4];
    float  psp[4], psb[4];

    // hoisted per-thread scatter bases (constant across chunks)
    uint32_t abase[4], bbase[4];
#pragma unroll
    for (int p = 0; p < 4; p++) {
        int q = tid + 256 * p;
        {   // A: edge (o_l = q>>3, ii = q&7)
            int o_l = q >> 3, ii = q & 7;
            int mt = o_l >> 4, r = o_l & 15;
            int ln = (r & 7) * 4 + (ii & 3);
            int word = ((ii >> 2) << 1) + (r >> 3);
            abase[p] = (mt * 32 + ln) * 4 + word;       // + g*1024
        }
        {   // B: edge (b = q&127, ii = q>>7)
            int b = q & 127, ii = q >> 7;
            int nt = b >> 3;
            int ln = (b & 7) * 4 + (ii & 3);
            bbase[p] = (nt * 32 + ln) * 2 + (ii >> 2);  // + g*1024
        }
    }

    auto ldgA = [&](int ib) {
#pragma unroll
        for (int p = 0; p < 4; p++) {
            int q = tid + 256 * p;
            int o_l = q >> 3, ii = q & 7;
            int e = (o0 + o_l) * IN_ + ib + ii;
            pc0[p] = ((const float4*)coef1)[e * 2];
            pc1[p] = ((const float4*)coef1)[e * 2 + 1];
            psp[p] = ssp1[e];
            psb[p] = sb1[e];
        }
    };
    auto stsA = [&](uint32_t offA) {
        uint32_t* As = (uint32_t*)(smem + offA);
#pragma unroll
        for (int p = 0; p < 4; p++) {
            uint32_t* base = As + abase[p];
            float sp = psp[p];
            base[0 * 1024] = tf32r(sp * pc0[p].x);
            base[1 * 1024] = tf32r(sp * pc0[p].y);
            base[2 * 1024] = tf32r(sp * pc0[p].z);
            base[3 * 1024] = tf32r(sp * pc0[p].w);
            base[4 * 1024] = tf32r(sp * pc1[p].x);
            base[5 * 1024] = tf32r(sp * pc1[p].y);
            base[6 * 1024] = tf32r(sp * pc1[p].z);
            base[7 * 1024] = tf32r(sp * pc1[p].w);
            base[8 * 1024] = tf32r(psb[p]);
        }
    };
    auto prodB = [&](int coff, uint32_t offB) {
        uint32_t* Bs = (uint32_t*)(smem + offB);
#pragma unroll
        for (int p = 0; p < 4; p++) {
            int q = tid + 256 * p;
            int b = q & 127, ii = q >> 7;
            float xv = xs[b * XS_PITCH + coff + ii];
            uint32_t* base = Bs + bbase[p];
            // zero-fill the 8 basis planes, then scatter the 4 nonzero weights
#pragma unroll
            for (int g = 0; g < 8; g++) base[g * 1024] = 0u;
            Bsp bs = bspline4(xv);
            float w[4] = { bs.w0, bs.w1, bs.w2, bs.w3 };
#pragma unroll
            for (int j = 0; j < 4; j++) {
                int g = bs.m - 3 + j;
                if (g >= 0 && g <= 7) base[g * 1024] = tf32r(w[j]);
            }
            base[8 * 1024] = tf32r(silu_f(xv));
        }
    };
    auto consume = [&](uint32_t offA, uint32_t offB) {
        const float4* As = (const float4*)(smem + offA);
        const float2* Bs = (const float2*)(smem + offB);
#pragma unroll
        for (int ks = 0; ks < NKS; ks++) {
            uint32_t af[4][4], bf[4][2];
#pragma unroll
            for (int mi = 0; mi < 4; mi++) {
                float4 v = As[(ks * 8 + wm * 4 + mi) * 32 + lane];
                af[mi][0] = __float_as_uint(v.x); af[mi][1] = __float_as_uint(v.y);
                af[mi][2] = __float_as_uint(v.z); af[mi][3] = __float_as_uint(v.w);
            }
#pragma unroll
            for (int ni = 0; ni < 4; ni++) {
                float2 v = Bs[(ks * 16 + wn * 4 + ni) * 32 + lane];
                bf[ni][0] = __float_as_uint(v.x); bf[ni][1] = __float_as_uint(v.y);
            }
#pragma unroll
            for (int mi = 0; mi < 4; mi++)
#pragma unroll
                for (int ni = 0; ni < 4; ni++) mma8(acc[mi][ni], af[mi], bf[ni]);
        }
    };

    // --- pipeline: LDG(t+1); prodB(t+1); consume(t); stsA(t+1); sync ---
    ldgA(i0);
    __syncthreads();                 // xs ready
    prodB(0, SM_B0);
    stsA(SM_A0);
    __syncthreads();

    for (int t = 0; t < NCH; t++) {
        const uint32_t offA = (t & 1) ? SM_A1 : SM_A0;
        const uint32_t offB = (t & 1) ? SM_B1 : SM_B0;
        const uint32_t nfA  = (t & 1) ? SM_A0 : SM_A1;
        const uint32_t nfB  = (t & 1) ? SM_B0 : SM_B1;
        if (t + 1 < NCH) { ldgA(i0 + (t + 1) * 8); prodB((t + 1) * 8, nfB); }
        consume(offA, offB);
        if (t + 1 < NCH) stsA(nfA);
        __syncthreads();
    }

    // --- writeout: transpose through smem, coalesced float4 partial stores ---
    {
        float* S = (float*)(smem + SM_A0);
        const int r = lane >> 2, c = lane & 3;
#pragma unroll
        for (int mi = 0; mi < 4; mi++)
#pragma unroll
            for (int ni = 0; ni < 4; ni++)
#pragma unroll
                for (int w = 0; w < 4; w++) {
                    int o_l = (wm * 4 + mi) * 16 + r + 8 * (w >> 1);
                    int b_l = (wn * 4 + ni) * 8 + 2 * c + (w & 1);
                    S[b_l * SP + o_l] = acc[mi][ni][w];
                }
        __syncthreads();
        float* Y = g_Y1p + split * (B_ * H_);
#pragma unroll
        for (int p = 0; p < 16; p++) {
            int idx = tid + 256 * p;
            int bb = idx >> 5, o4 = idx & 31;
            float4 v = *(float4*)&S[bb * SP + o4 * 4];
            *(float4*)&Y[bb * H_ + o0 + o4 * 4] = v;
        }
    }
}

// ---------------------------------------------------------------------------
// K3a: split reduction, 256 CTAs (validated round 5).
// ---------------------------------------------------------------------------
__global__ void __launch_bounds__(256) k3a_reduce() {
    __shared__ float4 sred[8][32];
    const int t = threadIdx.x, c = blockIdx.x;
    const int lane = t & 31, w = t >> 5;
    const int out = c * 32 + lane;
    const int b = out >> 6, o4 = out & 63;

    const float4* P = (const float4*)g_Y1p;
    float4 acc = make_float4(0.f, 0.f, 0.f, 0.f);
#pragma unroll
    for (int k = 0; k < 8; k++) {
        int s = w * 8 + k;
        float4 v = P[(s * B_ + b) * (H_ / 4) + o4];
        acc.x += v.x; acc.y += v.y; acc.z += v.z; acc.w += v.w;
    }
    sred[w][lane] = acc;
    __syncthreads();
    if (t < 32) {
        float4 a = sred[0][t];
#pragma unroll
        for (int j = 1; j < 8; j++) {
            float4 v = sred[j][t];
            a.x += v.x; a.y += v.y; a.z += v.z; a.w += v.w;
        }
        ((float4*)g_Y1)[c * 32 + t] = a;
    }
}

// ---------------------------------------------------------------------------
// K3b: layer 2, shfl reduction (validated round 5).
// ---------------------------------------------------------------------------
__global__ void __launch_bounds__(256) k3b_layer2(const float* __restrict__ coef2,
                                                 const float* __restrict__ sb2,
                                                 const float* __restrict__ ssp2,
                                                 float* __restrict__ out) {
    const int b = blockIdx.x;
    const int t = threadIdx.x;
    const int lane = t & 31, w = t >> 5;

    float h = selu_f(g_Y1[b * H_ + t]);
    Bsp bs = bspline4(h);
    float f0 = silu_f(h);
    float fb[8];
#pragma unroll
    for (int g = 0; g < 8; g++) fb[g] = bsp_at(bs, g);

    __shared__ float red[OUT_ * 8];
    float val[OUT_];
#pragma unroll
    for (int o = 0; o < OUT_; o++) {
        int e = o * H_ + t;
        float4 c0 = ((const float4*)coef2)[e * 2];
        float4 c1 = ((const float4*)coef2)[e * 2 + 1];
        float sp = ssp2[e];
        float spline = fb[0] * c0.x + fb[1] * c0.y + fb[2] * c0.z + fb[3] * c0.w
                     + fb[4] * c1.x + fb[5] * c1.y + fb[6] * c1.z + fb[7] * c1.w;
        val[o] = sb2[e] * f0 + sp * spline;
    }
#pragma unroll
    for (int o = 0; o < OUT_; o++) {
#pragma unroll
        for (int off = 16; off > 0; off >>= 1)
            val[o] += __shfl_down_sync(0xFFFFFFFFu, val[o], off);
    }
    if (lane == 0) {
#pragma unroll
        for (int o = 0; o < OUT_; o++) red[o * 8 + w] = val[o];
    }
    __syncthreads();
    if (t < OUT_) {
        float s = 0.0f;
#pragma unroll
        for (int j = 0; j < 8; j++) s += red[t * 8 + j];
        out[b * OUT_ + t] = s;
    }
}

// ---------------------------------------------------------------------------
extern "C" void kernel_launch(void* const* d_in, const int* in_sizes, int n_in,
                              void* d_out, int out_size) {
    const float* x     = (const float*)d_in[0];
    const float* coef1 = (const float*)d_in[1];
    const float* sb1   = (const float*)d_in[2];
    const float* ssp1  = (const float*)d_in[3];
    const float* coef2 = (const float*)d_in[4];
    const float* sb2   = (const float*)d_in[5];
    const float* ssp2  = (const float*)d_in[6];
    float* out = (float*)d_out;

    cudaFuncSetAttribute(k2_mma, cudaFuncAttributeMaxDynamicSharedMemorySize, SMEM_TOTAL);
    k2_mma<<<dim3(2, KSPLIT), 256, SMEM_TOTAL>>>(x, coef1, sb1, ssp1);
    k3a_reduce<<<(B_ * H_) / (32 * 4), 256>>>();
    k3b_layer2<<<B_, 256>>>(coef2, sb2, ssp2, out);
}

// round 7
// speedup vs baseline: 1.0650x; 1.0650x over previous
#include <cuda_runtime.h>
#include <cstdint>

// ---------------------------------------------------------------------------
// KAN 2-layer fused, round 7: conflict-free B scatter + 2 CTAs/SM.
//   D[o,b] = sum_{i,g} W[o,i,g] * f_g(x[b,i])
//   f = {basis_0..7(x), silu(x)},  W = {ssp*coef_0..7, sb}
//   g-major chunk K layout: kk = g*8 + ii  (plane stride A 4KB, B 2KB)
//   K2 CTA: M=128 (o) x N=64 (b) x K=432; grid (2 o x 2 b x 64 splits)=256.
// ---------------------------------------------------------------------------

#define B_     128
#define IN_    3072
#define H_     256
#define OUT_   10
#define KSPLIT 64
#define IPC    48          // inputs per CTA
#define NCH    6           // chunks of 8 inputs
#define NKS    9           // k-steps of 8 per chunk (9 feature planes)
#define NB     64          // batch rows per CTA

__device__ float g_Y1p[KSPLIT * B_ * H_];    // layer-1 partials [split][b][o]
__device__ float g_Y1[B_ * H_];              // reduced layer-1 pre-activation

// ---- dynamic smem layout: A tiles 36KB, B tiles 18KB -----------------------
#define SM_A0    0
#define SM_A1    36864
#define SM_B0    73728
#define SM_B1    (SM_B0 + 18432)
#define SMEM_TOTAL (SM_B1 + 18432)           // 110592 B -> 2 CTAs/SM
#define SP       132

// ---- helpers ---------------------------------------------------------------
__device__ __forceinline__ uint32_t tf32r(float x) {
    uint32_t r;
    asm("cvt.rna.tf32.f32 %0, %1;" : "=r"(r) : "f"(x));
    return r;
}
__device__ __forceinline__ void mma8(float d[4], const uint32_t a[4], const uint32_t b[2]) {
    asm volatile("mma.sync.aligned.m16n8k8.row.col.f32.tf32.tf32.f32 "
        "{%0,%1,%2,%3}, {%4,%5,%6,%7}, {%8,%9}, {%0,%1,%2,%3};"
        : "+f"(d[0]), "+f"(d[1]), "+f"(d[2]), "+f"(d[3])
        : "r"(a[0]), "r"(a[1]), "r"(a[2]), "r"(a[3]), "r"(b[0]), "r"(b[1]));
}
__device__ __forceinline__ float silu_f(float x) { return x / (1.0f + __expf(-x)); }
__device__ __forceinline__ float selu_f(float x) {
    const float scale = 1.0507009873554805f;
    const float alpha = 1.6732632423543772f;
    return x > 0.0f ? scale * x : scale * alpha * expm1f(x);
}

// Closed-form cubic B-spline on uniform extended grid t_j = -2.2 + 0.4 j
// (validated rounds 4-6 vs Cox-de-Boor; rel_err ~1e-5 end to end).
struct Bsp { float w0, w1, w2, w3; int m; };
__device__ __forceinline__ Bsp bspline4(float x) {
    Bsp r;
    float tpos = (x + 2.2f) * 2.5f;
    float mf = floorf(tpos);
    r.m = (int)mf;
    float u = tpos - mf;
    float u2 = u * u, u3 = u2 * u, om = 1.0f - u;
    bool valid = (x >= -2.2f) && (r.m <= 10);
    float s = valid ? (1.0f / 6.0f) : 0.0f;
    r.w0 = om * om * om * s;
    r.w1 = (3.0f * u3 - 6.0f * u2 + 4.0f) * s;
    r.w2 = (-3.0f * u3 + 3.0f * u2 + 3.0f * u + 1.0f) * s;
    r.w3 = u3 * s;
    return r;
}
__device__ __forceinline__ float bsp_at(const Bsp& r, int g) {
    int d = r.m - g;
    float v = 0.0f;
    v = (d == 3) ? r.w0 : v;
    v = (d == 2) ? r.w1 : v;
    v = (d == 1) ? r.w2 : v;
    v = (d == 0) ? r.w3 : v;
    return v;
}

// ---------------------------------------------------------------------------
// K2: layer-1 GEMM on mma.sync.
//   A_s[g][mt8][lane32][word4]  (plane stride 1024 u32)
//   B_s[g][nt8][lane32][word2]  (plane stride  512 u32)
// B producer edges: ii = q&7, b = q>>3  -> warp stores hit all 32 banks.
// ---------------------------------------------------------------------------
__global__ void __launch_bounds__(256, 2) k2_mma(const float* __restrict__ x,
                                                const float* __restrict__ coef1,
                                                const float* __restrict__ sb1,
                                                const float* __restrict__ ssp1) {
    extern __shared__ __align__(16) char smem[];

    const int tid  = threadIdx.x;
    const int lane = tid & 31;
    const int wid  = tid >> 5;
    const int wm   = wid >> 2;          // 0..1 : o 64 per warp-row
    const int wn   = wid & 3;           // 0..3 : b 16 per warp-col
    const int o0   = (blockIdx.x >> 1) * 128;
    const int b0   = (blockIdx.x & 1) * NB;
    const int split = blockIdx.y;
    const int i0   = split * IPC;

    float acc[4][2][4];
#pragma unroll
    for (int mi = 0; mi < 4; mi++)
#pragma unroll
        for (int ni = 0; ni < 2; ni++)
#pragma unroll
            for (int w = 0; w < 4; w++) acc[mi][ni][w] = 0.0f;

    // ---- hoisted scatter bases ----
    uint32_t abase[4];
#pragma unroll
    for (int p = 0; p < 4; p++) {       // A edge: o_l = q>>3, ii = q&7
        int q = tid + 256 * p;
        int o_l = q >> 3, ii = q & 7;
        int mt = o_l >> 4, r = o_l & 15;
        int ln = (r & 7) * 4 + (ii & 3);
        int word = ((ii >> 2) << 1) + (r >> 3);
        abase[p] = (mt * 32 + ln) * 4 + word;            // + g*1024
    }
    uint32_t bbase[2];
    int      bb_[2], bi_[2];
#pragma unroll
    for (int p = 0; p < 2; p++) {       // B edge: b = q>>3, ii = q&7
        int q = tid + 256 * p;
        int b = q >> 3, ii = q & 7;
        int nt = b >> 3;
        int ln = (b & 7) * 4 + (ii & 3);
        bbase[p] = (nt * 32 + ln) * 2 + (ii >> 2);       // + g*512
        bb_[p] = b; bi_[p] = ii;
    }

    // ---- staging registers ----
    float4 pc0[4], pc1[4];
    float  psp[4], psb[4];
    float  px[2];

    auto ldgA = [&](int ib) {
#pragma unroll
        for (int p = 0; p < 4; p++) {
            int q = tid + 256 * p;
            int o_l = q >> 3, ii = q & 7;
            int e = (o0 + o_l) * IN_ + ib + ii;
            pc0[p] = ((const float4*)coef1)[e * 2];
            pc1[p] = ((const float4*)coef1)[e * 2 + 1];
            psp[p] = ssp1[e];
            psb[p] = sb1[e];
        }
    };
    auto ldgB = [&](int ib) {
#pragma unroll
        for (int p = 0; p < 2; p++)
            px[p] = x[(b0 + bb_[p]) * IN_ + ib + bi_[p]];
    };
    auto stsA = [&](uint32_t offA) {
        uint32_t* As = (uint32_t*)(smem + offA);
#pragma unroll
        for (int p = 0; p < 4; p++) {
            uint32_t* base = As + abase[p];
            float sp = psp[p];
            base[0 * 1024] = tf32r(sp * pc0[p].x);
            base[1 * 1024] = tf32r(sp * pc0[p].y);
            base[2 * 1024] = tf32r(sp * pc0[p].z);
            base[3 * 1024] = tf32r(sp * pc0[p].w);
            base[4 * 1024] = tf32r(sp * pc1[p].x);
            base[5 * 1024] = tf32r(sp * pc1[p].y);
            base[6 * 1024] = tf32r(sp * pc1[p].z);
            base[7 * 1024] = tf32r(sp * pc1[p].w);
            base[8 * 1024] = tf32r(psb[p]);
        }
    };
    auto prodB = [&](uint32_t offB) {
        uint32_t* Bs = (uint32_t*)(smem + offB);
#pragma unroll
        for (int p = 0; p < 2; p++) {
            float xv = px[p];
            uint32_t* base = Bs + bbase[p];
#pragma unroll
            for (int g = 0; g < 8; g++) base[g * 512] = 0u;   // conflict-free
            Bsp bs = bspline4(xv);
            float w[4] = { bs.w0, bs.w1, bs.w2, bs.w3 };
#pragma unroll
            for (int j = 0; j < 4; j++) {
                int g = bs.m - 3 + j;
                if (g >= 0 && g <= 7) base[g * 512] = tf32r(w[j]);
            }
            base[8 * 512] = tf32r(silu_f(xv));
        }
    };
    auto consume = [&](uint32_t offA, uint32_t offB) {
        const float4* As = (const float4*)(smem + offA);
        const float2* Bs = (const float2*)(smem + offB);
#pragma unroll
        for (int ks = 0; ks < NKS; ks++) {
            uint32_t af[4][4], bf[2][2];
#pragma unroll
            for (int mi = 0; mi < 4; mi++) {
                float4 v = As[(ks * 8 + wm * 4 + mi) * 32 + lane];
                af[mi][0] = __float_as_uint(v.x); af[mi][1] = __float_as_uint(v.y);
                af[mi][2] = __float_as_uint(v.z); af[mi][3] = __float_as_uint(v.w);
            }
#pragma unroll
            for (int ni = 0; ni < 2; ni++) {
                float2 v = Bs[(ks * 8 + wn * 2 + ni) * 32 + lane];
                bf[ni][0] = __float_as_uint(v.x); bf[ni][1] = __float_as_uint(v.y);
            }
#pragma unroll
            for (int mi = 0; mi < 4; mi++)
#pragma unroll
                for (int ni = 0; ni < 2; ni++) mma8(acc[mi][ni], af[mi], bf[ni]);
        }
    };

    // --- pipeline (round-4 order): ldg(t+1); consume(t); sts(t+1); sync ---
    ldgA(i0); ldgB(i0);
    stsA(SM_A0); prodB(SM_B0);
    __syncthreads();

    for (int t = 0; t < NCH; t++) {
        const uint32_t offA = (t & 1) ? SM_A1 : SM_A0;
        const uint32_t offB = (t & 1) ? SM_B1 : SM_B0;
        const uint32_t nfA  = (t & 1) ? SM_A0 : SM_A1;
        const uint32_t nfB  = (t & 1) ? SM_B0 : SM_B1;
        if (t + 1 < NCH) { ldgA(i0 + (t + 1) * 8); ldgB(i0 + (t + 1) * 8); }
        consume(offA, offB);
        if (t + 1 < NCH) { stsA(nfA); prodB(nfB); }
        __syncthreads();
    }

    // --- writeout: transpose through smem, coalesced float4 partial stores ---
    {
        float* S = (float*)(smem + SM_A0);      // [64 b][pitch SP]
        const int r = lane >> 2, c = lane & 3;
#pragma unroll
        for (int mi = 0; mi < 4; mi++)
#pragma unroll
            for (int ni = 0; ni < 2; ni++)
#pragma unroll
                for (int w = 0; w < 4; w++) {
                    int o_l = (wm * 4 + mi) * 16 + r + 8 * (w >> 1);
                    int b_l = (wn * 2 + ni) * 8 + 2 * c + (w & 1);
                    S[b_l * SP + o_l] = acc[mi][ni][w];
                }
        __syncthreads();
        float* Y = g_Y1p + split * (B_ * H_);
#pragma unroll
        for (int p = 0; p < 8; p++) {
            int idx = tid + 256 * p;
            int bb = idx >> 5, o4 = idx & 31;
            float4 v = *(float4*)&S[bb * SP + o4 * 4];
            *(float4*)&Y[(b0 + bb) * H_ + o0 + o4 * 4] = v;
        }
    }
}

// ---------------------------------------------------------------------------
// K3a: split reduction, 256 CTAs (validated round 5).
// ---------------------------------------------------------------------------
__global__ void __launch_bounds__(256) k3a_reduce() {
    __shared__ float4 sred[8][32];
    const int t = threadIdx.x, c = blockIdx.x;
    const int lane = t & 31, w = t >> 5;
    const int out = c * 32 + lane;
    const int b = out >> 6, o4 = out & 63;

    const float4* P = (const float4*)g_Y1p;
    float4 acc = make_float4(0.f, 0.f, 0.f, 0.f);
#pragma unroll
    for (int k = 0; k < 8; k++) {
        int s = w * 8 + k;
        float4 v = P[(s * B_ + b) * (H_ / 4) + o4];
        acc.x += v.x; acc.y += v.y; acc.z += v.z; acc.w += v.w;
    }
    sred[w][lane] = acc;
    __syncthreads();
    if (t < 32) {
        float4 a = sred[0][t];
#pragma unroll
        for (int j = 1; j < 8; j++) {
            float4 v = sred[j][t];
            a.x += v.x; a.y += v.y; a.z += v.z; a.w += v.w;
        }
        ((float4*)g_Y1)[c * 32 + t] = a;
    }
}

// ---------------------------------------------------------------------------
// K3b: layer 2, shfl reduction (validated round 5).
// ---------------------------------------------------------------------------
__global__ void __launch_bounds__(256) k3b_layer2(const float* __restrict__ coef2,
                                                 const float* __restrict__ sb2,
                                                 const float* __restrict__ ssp2,
                                                 float* __restrict__ out) {
    const int b = blockIdx.x;
    const int t = threadIdx.x;
    const int lane = t & 31, w = t >> 5;

    float h = selu_f(g_Y1[b * H_ + t]);
    Bsp bs = bspline4(h);
    float f0 = silu_f(h);
    float fb[8];
#pragma unroll
    for (int g = 0; g < 8; g++) fb[g] = bsp_at(bs, g);

    __shared__ float red[OUT_ * 8];
    float val[OUT_];
#pragma unroll
    for (int o = 0; o < OUT_; o++) {
        int e = o * H_ + t;
        float4 c0 = ((const float4*)coef2)[e * 2];
        float4 c1 = ((const float4*)coef2)[e * 2 + 1];
        float sp = ssp2[e];
        float spline = fb[0] * c0.x + fb[1] * c0.y + fb[2] * c0.z + fb[3] * c0.w
                     + fb[4] * c1.x + fb[5] * c1.y + fb[6] * c1.z + fb[7] * c1.w;
        val[o] = sb2[e] * f0 + sp * spline;
    }
#pragma unroll
    for (int o = 0; o < OUT_; o++) {
#pragma unroll
        for (int off = 16; off > 0; off >>= 1)
            val[o] += __shfl_down_sync(0xFFFFFFFFu, val[o], off);
    }
    if (lane == 0) {
#pragma unroll
        for (int o = 0; o < OUT_; o++) red[o * 8 + w] = val[o];
    }
    __syncthreads();
    if (t < OUT_) {
        float s = 0.0f;
#pragma unroll
        for (int j = 0; j < 8; j++) s += red[t * 8 + j];
        out[b * OUT_ + t] = s;
    }
}

// ---------------------------------------------------------------------------
extern "C" void kernel_launch(void* const* d_in, const int* in_sizes, int n_in,
                              void* d_out, int out_size) {
    const float* x     = (const float*)d_in[0];
    const float* coef1 = (const float*)d_in[1];
    const float* sb1   = (const float*)d_in[2];
    const float* ssp1  = (const float*)d_in[3];
    const float* coef2 = (const float*)d_in[4];
    const float* sb2   = (const float*)d_in[5];
    const float* ssp2  = (const float*)d_in[6];
    float* out = (float*)d_out;

    cudaFuncSetAttribute(k2_mma, cudaFuncAttributeMaxDynamicSharedMemorySize, SMEM_TOTAL);
    k2_mma<<<dim3(4, KSPLIT), 256, SMEM_TOTAL>>>(x, coef1, sb1, ssp1);
    k3a_reduce<<<(B_ * H_) / (32 * 4), 256>>>();
    k3b_layer2<<<B_, 256>>>(coef2, sb2, ssp2, out);
}